// round 16
// baseline (speedup 1.0000x reference)
#include <cuda_runtime.h>
#include <cuda_bf16.h>
#include <cstdint>

// Problem dims (fixed by the reference)
#define Bdim  8
#define Sdim  1024
#define Ddim  1024
#define Hdim  16
#define DKdim 64
#define Mdim  (Bdim * Sdim)   // 8192 rows
#define K2    2048            // split width (hi | lo)

// ---------------------------------------------------------------------------
// Scratch (__device__ globals; no cudaMalloc allowed)
// ---------------------------------------------------------------------------
__device__ __nv_bfloat16 g_xs  [(size_t)Mdim * K2];        // x split [M,2048]
__device__ __nv_bfloat16 g_wqkv[(size_t)3 * Ddim * K2];    // Wq|Wk|Wv ^T split
__device__ __nv_bfloat16 g_wo  [(size_t)Ddim * K2];        // Wo^T split
__device__ __nv_bfloat16 g_qs  [(size_t)Mdim * K2];        // Q split (pre-scaled)
__device__ __nv_bfloat16 g_ks  [(size_t)Mdim * K2];
__device__ __nv_bfloat16 g_vs  [(size_t)Mdim * K2];
__device__ __nv_bfloat16 g_attb[(size_t)Mdim * K2];        // attn out split

// ---------------------------------------------------------------------------
// Helpers (arch-agnostic PTX only: cp.async, ldmatrix, mma.sync)
// ---------------------------------------------------------------------------
__device__ __forceinline__ uint32_t smem_u32(const void* p) {
    uint32_t a;
    asm("{ .reg .u64 t; cvta.to.shared.u64 t, %1; cvt.u32.u64 %0, t; }"
        : "=r"(a) : "l"(p));
    return a;
}

__device__ __forceinline__ void cp_async16(uint32_t dst, const void* src) {
    asm volatile("cp.async.cg.shared.global [%0], [%1], 16;"
                 :: "r"(dst), "l"(src) : "memory");
}
__device__ __forceinline__ void cp_commit() {
    asm volatile("cp.async.commit_group;" ::: "memory");
}
template <int N>
__device__ __forceinline__ void cp_wait() {
    asm volatile("cp.async.wait_group %0;" :: "n"(N) : "memory");
}

__device__ __forceinline__ void ldsm_x4(uint32_t& r0, uint32_t& r1,
                                        uint32_t& r2, uint32_t& r3, uint32_t a) {
    asm volatile("ldmatrix.sync.aligned.m8n8.x4.shared.b16 {%0,%1,%2,%3}, [%4];"
                 : "=r"(r0), "=r"(r1), "=r"(r2), "=r"(r3) : "r"(a));
}
__device__ __forceinline__ void ldsm_x4_t(uint32_t& r0, uint32_t& r1,
                                          uint32_t& r2, uint32_t& r3, uint32_t a) {
    asm volatile("ldmatrix.sync.aligned.m8n8.x4.trans.shared.b16 {%0,%1,%2,%3}, [%4];"
                 : "=r"(r0), "=r"(r1), "=r"(r2), "=r"(r3) : "r"(a));
}

__device__ __forceinline__ void mma_bf16(float* d, const uint32_t* a,
                                         const uint32_t* b) {
    asm volatile(
        "mma.sync.aligned.m16n8k16.row.col.f32.bf16.bf16.f32 "
        "{%0,%1,%2,%3}, {%4,%5,%6,%7}, {%8,%9}, {%0,%1,%2,%3};"
        : "+f"(d[0]), "+f"(d[1]), "+f"(d[2]), "+f"(d[3])
        : "r"(a[0]), "r"(a[1]), "r"(a[2]), "r"(a[3]), "r"(b[0]), "r"(b[1]));
}

__device__ __forceinline__ uint32_t bfpack(__nv_bfloat16 a, __nv_bfloat16 b) {
    return ((uint32_t)__bfloat16_as_ushort(b) << 16) | (uint32_t)__bfloat16_as_ushort(a);
}

// Pack (x -> low, y -> high) into bf16x2 in ONE cvt instruction.
__device__ __forceinline__ uint32_t cvt2_bf16(float x, float y) {
    uint32_t r;
    asm("cvt.rn.bf16x2.f32 %0, %1, %2;" : "=r"(r) : "f"(y), "f"(x));
    return r;
}

// Pack (x,y) -> bf16x2 hi-plane + residual lo-plane (x in low half).
#define SPLITPK(dh, dl, x, y)                                                  \
    {                                                                          \
        float _x = (x), _y = (y);                                              \
        uint32_t _h = cvt2_bf16(_x, _y);                                       \
        float _fx = __uint_as_float(_h << 16);                                 \
        float _fy = __uint_as_float(_h & 0xffff0000u);                         \
        (dh) = _h;                                                             \
        (dl) = cvt2_bf16(_x - _fx, _y - _fy);                                  \
    }

// Swizzle inside a [rows x 32 bf16] tile (64B rows, 4 chunks)
__device__ __forceinline__ uint32_t swz(int row, int chunk) {
    return (uint32_t)(row * 64 + ((chunk ^ ((row >> 1) & 3)) << 4));
}
// Swizzle inside a [rows x 64 bf16] tile (128B rows, 8 chunks)
__device__ __forceinline__ uint32_t sw64o(int row, int chunk) {
    return (uint32_t)(row * 128 + ((chunk ^ (row & 7)) << 4));
}

// ---------------------------------------------------------------------------
// Conversion kernels
// ---------------------------------------------------------------------------
__global__ __launch_bounds__(256) void split_x_kernel(const float* __restrict__ X,
                                                      __nv_bfloat16* __restrict__ Y) {
    size_t t = (size_t)blockIdx.x * 256 + threadIdx.x;
    size_t e = t * 4;
    int row = (int)(e >> 10);
    int col = (int)(e & 1023);
    float4 v = *(const float4*)(X + e);
    uint2 ph, pl;
    SPLITPK(ph.x, pl.x, v.x, v.y);
    SPLITPK(ph.y, pl.y, v.z, v.w);
    *(uint2*)(Y + (size_t)row * K2 + col)        = ph;
    *(uint2*)(Y + (size_t)row * K2 + 1024 + col) = pl;
}

// All four weights in one launch (z selects W); dest: Wq|Wk|Wv -> Yqkv, Wo -> Yo
__global__ __launch_bounds__(256) void wsplit4_kernel(
    const float* __restrict__ W0, const float* __restrict__ W1,
    const float* __restrict__ W2, const float* __restrict__ W3,
    __nv_bfloat16* __restrict__ Yqkv, __nv_bfloat16* __restrict__ Yo)
{
    __shared__ float t[32][33];
    const int z = blockIdx.z;
    const float* W = (z == 0) ? W0 : (z == 1) ? W1 : (z == 2) ? W2 : W3;
    __nv_bfloat16* Y = (z < 3) ? (Yqkv + (size_t)z * Ddim * K2) : Yo;

    int k0 = blockIdx.x * 32, n0 = blockIdx.y * 32;
    int tx = threadIdx.x, ty = threadIdx.y;   // 32 x 8
#pragma unroll
    for (int i = 0; i < 4; i++)
        t[ty + 8 * i][tx] = W[(size_t)(k0 + ty + 8 * i) * 1024 + n0 + tx];
    __syncthreads();
#pragma unroll
    for (int i = 0; i < 4; i++) {
        int n = n0 + ty + 8 * i;
        float v = t[tx][ty + 8 * i];
        __nv_bfloat16 h = __float2bfloat16(v);
        __nv_bfloat16 l = __float2bfloat16(v - __bfloat162float(h));
        Y[(size_t)n * K2 + k0 + tx]        = h;
        Y[(size_t)n * K2 + 1024 + k0 + tx] = l;
    }
}

// ---------------------------------------------------------------------------
// bf16-split GEMM (3-term), all-planes-per-chunk, 3-stage pipeline,
// ONE barrier per k-iteration (gemm3 is register-bound at 2 CTA/SM, so the
// extra stage costs no occupancy).
// mode 0: fused QKV epilogue (route by 1024-col region, bias+scale, split out)
// mode 1: fp32 out Cf = A*B^T + bias0.
// ---------------------------------------------------------------------------
#define GSMEM (3 * 32768)

__global__ __launch_bounds__(256) void gemm3(
    const __nv_bfloat16* __restrict__ A2,
    const __nv_bfloat16* __restrict__ B2,
    const float* __restrict__ bias0,
    const float* __restrict__ bias1,
    const float* __restrict__ bias2,
    __nv_bfloat16* __restrict__ Cq,
    __nv_bfloat16* __restrict__ Ck,
    __nv_bfloat16* __restrict__ Cv,
    float* __restrict__ Cf,
    int mode, int N)
{
    extern __shared__ __align__(128) char smraw[];
    const uint32_t sm0 = smem_u32(smraw);

    const int tid  = threadIdx.x;
    const int lane = tid & 31;
    const int warp = tid >> 5;
    const int wm   = warp & 1;
    const int wn   = warp >> 1;
    const int brow = blockIdx.y * 128;
    const int bcol = blockIdx.x * 128;

    float acc[4][4][4];
#pragma unroll
    for (int i = 0; i < 4; i++)
#pragma unroll
        for (int j = 0; j < 4; j++)
#pragma unroll
            for (int e = 0; e < 4; e++) acc[i][j][e] = 0.f;

    const int r0 = tid >> 2,         c0 = tid & 3;
    const int r1 = (tid + 256) >> 2, c1 = (tid + 256) & 3;
    const uint32_t so0 = swz(r0, c0), so1 = swz(r1, c1);

    const int lrow  = lane & 15;
    const int lksel = lane >> 4;

#define ISSUE(it, stage)                                                       \
    do {                                                                       \
        int _kt = (it);                                                        \
        const __nv_bfloat16* _A = A2 + (size_t)brow * K2 + _kt * 32;           \
        const __nv_bfloat16* _B = B2 + (size_t)bcol * K2 + _kt * 32;           \
        uint32_t _s = sm0 + (stage) * 32768;                                   \
        cp_async16(_s + so0,          _A + (size_t)r0 * K2 + c0 * 8);          \
        cp_async16(_s + so1,          _A + (size_t)r1 * K2 + c1 * 8);          \
        cp_async16(_s + 8192  + so0,  _A + (size_t)r0 * K2 + 1024 + c0 * 8);   \
        cp_async16(_s + 8192  + so1,  _A + (size_t)r1 * K2 + 1024 + c1 * 8);   \
        cp_async16(_s + 16384 + so0,  _B + (size_t)r0 * K2 + c0 * 8);          \
        cp_async16(_s + 16384 + so1,  _B + (size_t)r1 * K2 + c1 * 8);          \
        cp_async16(_s + 24576 + so0,  _B + (size_t)r0 * K2 + 1024 + c0 * 8);   \
        cp_async16(_s + 24576 + so1,  _B + (size_t)r1 * K2 + 1024 + c1 * 8);   \
        cp_commit();                                                           \
    } while (0)

    ISSUE(0, 0);
    ISSUE(1, 1);

    for (int it = 0; it < 32; it++) {
        if (it == 31) { cp_wait<0>(); } else { cp_wait<1>(); }
        __syncthreads();
        if (it + 2 < 32) ISSUE(it + 2, (it + 2) % 3);

        const uint32_t sAh = sm0 + (it % 3) * 32768;
        const uint32_t sAl = sAh + 8192;
        const uint32_t sBh = sAh + 16384;
        const uint32_t sBl = sAh + 24576;

#pragma unroll
        for (int ks = 0; ks < 2; ks++) {
            const int chunk = ks * 2 + lksel;
            uint32_t ah[4][4], al[4][4], b[4][2];
#pragma unroll
            for (int mi = 0; mi < 4; mi++)
                ldsm_x4(ah[mi][0], ah[mi][1], ah[mi][2], ah[mi][3],
                        sAh + swz(wm * 64 + mi * 16 + lrow, chunk));
#pragma unroll
            for (int nj = 0; nj < 2; nj++) {
                uint32_t t0, t1, t2, t3;
                ldsm_x4(t0, t1, t2, t3,
                        sBh + swz(wn * 32 + nj * 16 + lrow, chunk));
                b[nj * 2 + 0][0] = t0;  b[nj * 2 + 1][0] = t1;
                b[nj * 2 + 0][1] = t2;  b[nj * 2 + 1][1] = t3;
            }
#pragma unroll
            for (int mi = 0; mi < 4; mi++)
#pragma unroll
                for (int ni = 0; ni < 4; ni++)
                    mma_bf16(acc[mi][ni], ah[mi], b[ni]);

#pragma unroll
            for (int mi = 0; mi < 4; mi++)
                ldsm_x4(al[mi][0], al[mi][1], al[mi][2], al[mi][3],
                        sAl + swz(wm * 64 + mi * 16 + lrow, chunk));
#pragma unroll
            for (int mi = 0; mi < 4; mi++)
#pragma unroll
                for (int ni = 0; ni < 4; ni++)
                    mma_bf16(acc[mi][ni], al[mi], b[ni]);

#pragma unroll
            for (int nj = 0; nj < 2; nj++) {
                uint32_t t0, t1, t2, t3;
                ldsm_x4(t0, t1, t2, t3,
                        sBl + swz(wn * 32 + nj * 16 + lrow, chunk));
                b[nj * 2 + 0][0] = t0;  b[nj * 2 + 1][0] = t1;
                b[nj * 2 + 0][1] = t2;  b[nj * 2 + 1][1] = t3;
            }
#pragma unroll
            for (int mi = 0; mi < 4; mi++)
#pragma unroll
                for (int ni = 0; ni < 4; ni++)
                    mma_bf16(acc[mi][ni], ah[mi], b[ni]);
        }
    }
#undef ISSUE

    // ---- Epilogue ----
    if (mode == 0) {
        const int region = bcol >> 10;                  // 0:Q 1:K 2:V
        __nv_bfloat16* Cs  = (region == 0) ? Cq : (region == 1) ? Ck : Cv;
        const float*   bia = (region == 0) ? bias0 : (region == 1) ? bias1 : bias2;
        const float    scale = (region == 0) ? 0.125f : 1.0f;
        const int ncb = bcol & 1023;
#pragma unroll
        for (int mi = 0; mi < 4; mi++) {
#pragma unroll
            for (int ni = 0; ni < 4; ni++) {
                int r = brow + wm * 64 + mi * 16 + (lane >> 2);
                int c = ncb + wn * 32 + ni * 8 + (lane & 3) * 2;
                float bx = bia[c], by = bia[c + 1];
                float x0 = (acc[mi][ni][0] + bx) * scale;
                float x1 = (acc[mi][ni][1] + by) * scale;
                float x2 = (acc[mi][ni][2] + bx) * scale;
                float x3 = (acc[mi][ni][3] + by) * scale;
                uint32_t h01, l01, h23, l23;
                SPLITPK(h01, l01, x0, x1);
                SPLITPK(h23, l23, x2, x3);
                *(uint32_t*)(Cs + (size_t)r * K2 + c)              = h01;
                *(uint32_t*)(Cs + (size_t)r * K2 + 1024 + c)       = l01;
                *(uint32_t*)(Cs + (size_t)(r + 8) * K2 + c)        = h23;
                *(uint32_t*)(Cs + (size_t)(r + 8) * K2 + 1024 + c) = l23;
            }
        }
    } else {
#pragma unroll
        for (int mi = 0; mi < 4; mi++) {
#pragma unroll
            for (int ni = 0; ni < 4; ni++) {
                int r = brow + wm * 64 + mi * 16 + (lane >> 2);
                int c = bcol + wn * 32 + ni * 8 + (lane & 3) * 2;
                float bx = bias0[c], by = bias0[c + 1];
                *(float2*)(Cf + (size_t)r * N + c) =
                    make_float2(acc[mi][ni][0] + bx, acc[mi][ni][1] + by);
                *(float2*)(Cf + (size_t)(r + 8) * N + c) =
                    make_float2(acc[mi][ni][2] + bx, acc[mi][ni][3] + by);
            }
        }
    }
}

// ---------------------------------------------------------------------------
// Tensor-core flash attention (mma.sync bf16, 3-term split on both matmuls).
// CTA = 64 queries of one (b,h); 4 warps x 16 q-rows; 16 key-tiles of 64.
// 2-stage cp.async pipeline (32KB/stage) -> 66KB smem, 3 CTAs/SM.
// (Unchanged from R14 — proven config.)
// ---------------------------------------------------------------------------
#define ATTN_SMEM (65536 + 512)

__global__ __launch_bounds__(128) void attn_mma(
    const __nv_bfloat16* __restrict__ Qs,
    const __nv_bfloat16* __restrict__ Ks,
    const __nv_bfloat16* __restrict__ Vsrc,
    const int* __restrict__ masks,
    __nv_bfloat16* __restrict__ Ob)
{
    extern __shared__ __align__(128) char smraw[];
    const uint32_t sb = smem_u32(smraw);
    int* mskp = (int*)(smraw + 65536);

    const int tid  = threadIdx.x;
    const int lane = tid & 31;
    const int warp = tid >> 5;
    const int lrow  = lane & 15;
    const int lksel = lane >> 4;
    const int b = blockIdx.z, h = blockIdx.y;
    const int q0 = blockIdx.x * 64;

    const __nv_bfloat16* Qg = Qs   + (size_t)(b * Sdim + q0) * K2 + h * 64;
    const __nv_bfloat16* Kg = Ks   + (size_t)(b * Sdim) * K2 + h * 64;
    const __nv_bfloat16* Vg = Vsrc + (size_t)(b * Sdim) * K2 + h * 64;

    // ---- stage Q (hi/lo) through smem, extract fragments into registers ----
#pragma unroll
    for (int i = 0; i < 4; i++) {
        int idx = tid + i * 128;
        int r = idx >> 3, c = idx & 7;
        uint32_t off = sw64o(r, c);
        cp_async16(sb + off,        Qg + (size_t)r * K2 + c * 8);
        cp_async16(sb + 8192 + off, Qg + (size_t)r * K2 + 1024 + c * 8);
    }
    cp_commit();
    cp_wait<0>();
    __syncthreads();

    uint32_t aqh[4][4], aql[4][4];
#pragma unroll
    for (int ks = 0; ks < 4; ks++) {
        uint32_t off = sw64o(warp * 16 + lrow, ks * 2 + lksel);
        ldsm_x4(aqh[ks][0], aqh[ks][1], aqh[ks][2], aqh[ks][3], sb + off);
        ldsm_x4(aql[ks][0], aql[ks][1], aql[ks][2], aql[ks][3], sb + 8192 + off);
    }
    __syncthreads();

#define AISSUE(kt, stg)                                                         \
    do {                                                                        \
        const __nv_bfloat16* _K = Kg + (size_t)(kt) * 64 * K2;                  \
        const __nv_bfloat16* _V = Vg + (size_t)(kt) * 64 * K2;                  \
        uint32_t _s = sb + (stg) * 32768;                                       \
        _Pragma("unroll")                                                       \
        for (int _i = 0; _i < 4; _i++) {                                        \
            int _idx = tid + _i * 128;                                          \
            int _r = _idx >> 3, _c = _idx & 7;                                  \
            uint32_t _o = sw64o(_r, _c);                                        \
            cp_async16(_s + _o,         _K + (size_t)_r * K2 + _c * 8);         \
            cp_async16(_s + 8192 + _o,  _K + (size_t)_r * K2 + 1024 + _c * 8);  \
            cp_async16(_s + 16384 + _o, _V + (size_t)_r * K2 + _c * 8);         \
            cp_async16(_s + 24576 + _o, _V + (size_t)_r * K2 + 1024 + _c * 8);  \
        }                                                                       \
        if (tid < 64) mskp[(stg) * 64 + tid] = masks[b * Sdim + (kt) * 64 + tid]; \
        cp_commit();                                                            \
    } while (0)

    float m0 = -1e30f, m1 = -1e30f, l0 = 0.f, l1 = 0.f;
    float o[8][4];
#pragma unroll
    for (int dt = 0; dt < 8; dt++)
#pragma unroll
        for (int e = 0; e < 4; e++) o[dt][e] = 0.f;

    AISSUE(0, 0);

    for (int kt = 0; kt < 16; kt++) {
        const int st = kt & 1;
        if (kt + 1 < 16) {
            AISSUE(kt + 1, st ^ 1);
            cp_wait<1>();
        } else {
            cp_wait<0>();
        }
        __syncthreads();

        const uint32_t sK  = sb + st * 32768;
        const uint32_t sKl = sK + 8192;
        const uint32_t sV  = sK + 16384;
        const uint32_t sVl = sK + 24576;
        const int* mk = mskp + st * 64;

        // -------- scores: S = Qhi*Khi + Qlo*Khi + Qhi*Klo --------
        float sc[8][4];
#pragma unroll
        for (int nt = 0; nt < 8; nt++)
#pragma unroll
            for (int e = 0; e < 4; e++) sc[nt][e] = 0.f;

#pragma unroll
        for (int ks = 0; ks < 4; ks++) {
            uint32_t bk[8][2];
#pragma unroll
            for (int np = 0; np < 4; np++) {
                uint32_t t0, t1, t2, t3;
                ldsm_x4(t0, t1, t2, t3, sK + sw64o(np * 16 + lrow, ks * 2 + lksel));
                bk[np * 2][0] = t0;  bk[np * 2][1] = t2;
                bk[np * 2 + 1][0] = t1;  bk[np * 2 + 1][1] = t3;
            }
#pragma unroll
            for (int nt = 0; nt < 8; nt++) mma_bf16(sc[nt], aqh[ks], bk[nt]);
#pragma unroll
            for (int nt = 0; nt < 8; nt++) mma_bf16(sc[nt], aql[ks], bk[nt]);
#pragma unroll
            for (int np = 0; np < 4; np++) {
                uint32_t t0, t1, t2, t3;
                ldsm_x4(t0, t1, t2, t3, sKl + sw64o(np * 16 + lrow, ks * 2 + lksel));
                bk[np * 2][0] = t0;  bk[np * 2][1] = t2;
                bk[np * 2 + 1][0] = t1;  bk[np * 2 + 1][1] = t3;
            }
#pragma unroll
            for (int nt = 0; nt < 8; nt++) mma_bf16(sc[nt], aqh[ks], bk[nt]);
        }

        // -------- mask --------
#pragma unroll
        for (int nt = 0; nt < 8; nt++) {
            int k0 = nt * 8 + 2 * (lane & 3);
            if (mk[k0] == 0)     { sc[nt][0] = -1e9f; sc[nt][2] = -1e9f; }
            if (mk[k0 + 1] == 0) { sc[nt][1] = -1e9f; sc[nt][3] = -1e9f; }
        }

        // -------- online softmax (rows r = lane>>2 and r+8) --------
        float mx0 = -1e30f, mx1 = -1e30f;
#pragma unroll
        for (int nt = 0; nt < 8; nt++) {
            mx0 = fmaxf(mx0, fmaxf(sc[nt][0], sc[nt][1]));
            mx1 = fmaxf(mx1, fmaxf(sc[nt][2], sc[nt][3]));
        }
        mx0 = fmaxf(mx0, __shfl_xor_sync(0xffffffffu, mx0, 1));
        mx0 = fmaxf(mx0, __shfl_xor_sync(0xffffffffu, mx0, 2));
        mx1 = fmaxf(mx1, __shfl_xor_sync(0xffffffffu, mx1, 1));
        mx1 = fmaxf(mx1, __shfl_xor_sync(0xffffffffu, mx1, 2));

        float nm0 = fmaxf(m0, mx0), nm1 = fmaxf(m1, mx1);
        float cr0 = __expf(m0 - nm0), cr1 = __expf(m1 - nm1);
        float s0 = 0.f, s1 = 0.f;
#pragma unroll
        for (int nt = 0; nt < 8; nt++) {
            sc[nt][0] = __expf(sc[nt][0] - nm0);  s0 += sc[nt][0];
            sc[nt][1] = __expf(sc[nt][1] - nm0);  s0 += sc[nt][1];
            sc[nt][2] = __expf(sc[nt][2] - nm1);  s1 += sc[nt][2];
            sc[nt][3] = __expf(sc[nt][3] - nm1);  s1 += sc[nt][3];
        }
        s0 += __shfl_xor_sync(0xffffffffu, s0, 1);
        s0 += __shfl_xor_sync(0xffffffffu, s0, 2);
        s1 += __shfl_xor_sync(0xffffffffu, s1, 1);
        s1 += __shfl_xor_sync(0xffffffffu, s1, 2);
        l0 = l0 * cr0 + s0;  l1 = l1 * cr1 + s1;
        m0 = nm0;  m1 = nm1;
#pragma unroll
        for (int dt = 0; dt < 8; dt++) {
            o[dt][0] *= cr0;  o[dt][1] *= cr0;
            o[dt][2] *= cr1;  o[dt][3] *= cr1;
        }

        // -------- O += Phi*Vhi + Plo*Vhi + Phi*Vlo --------
#pragma unroll
        for (int ks = 0; ks < 4; ks++) {
            uint32_t ah[4], al[4];
            SPLITPK(ah[0], al[0], sc[2 * ks][0],     sc[2 * ks][1]);
            SPLITPK(ah[1], al[1], sc[2 * ks][2],     sc[2 * ks][3]);
            SPLITPK(ah[2], al[2], sc[2 * ks + 1][0], sc[2 * ks + 1][1]);
            SPLITPK(ah[3], al[3], sc[2 * ks + 1][2], sc[2 * ks + 1][3]);

            uint32_t bv[8][2];
#pragma unroll
            for (int dp = 0; dp < 4; dp++) {
                uint32_t t0, t1, t2, t3;
                ldsm_x4_t(t0, t1, t2, t3, sV + sw64o(ks * 16 + lrow, dp * 2 + lksel));
                bv[dp * 2][0] = t0;  bv[dp * 2][1] = t1;
                bv[dp * 2 + 1][0] = t2;  bv[dp * 2 + 1][1] = t3;
            }
#pragma unroll
            for (int dt = 0; dt < 8; dt++) mma_bf16(o[dt], ah, bv[dt]);
#pragma unroll
            for (int dt = 0; dt < 8; dt++) mma_bf16(o[dt], al, bv[dt]);
#pragma unroll
            for (int dp = 0; dp < 4; dp++) {
                uint32_t t0, t1, t2, t3;
                ldsm_x4_t(t0, t1, t2, t3, sVl + sw64o(ks * 16 + lrow, dp * 2 + lksel));
                bv[dp * 2][0] = t0;  bv[dp * 2][1] = t1;
                bv[dp * 2 + 1][0] = t2;  bv[dp * 2 + 1][1] = t3;
            }
#pragma unroll
            for (int dt = 0; dt < 8; dt++) mma_bf16(o[dt], ah, bv[dt]);
        }
        __syncthreads();
    }
#undef AISSUE

    // -------- normalize + write bf16 hi/lo split --------
    float i0 = 1.f / l0, i1 = 1.f / l1;
    int rg = b * Sdim + q0 + warp * 16 + (lane >> 2);
    int cb = h * 64 + 2 * (lane & 3);
    __nv_bfloat16* O0 = Ob + (size_t)rg * K2;
    __nv_bfloat16* O1 = Ob + (size_t)(rg + 8) * K2;
#pragma unroll
    for (int dt = 0; dt < 8; dt++) {
        int c = cb + dt * 8;
        uint32_t h01, l01, h23, l23;
        SPLITPK(h01, l01, o[dt][0] * i0, o[dt][1] * i0);
        SPLITPK(h23, l23, o[dt][2] * i1, o[dt][3] * i1);
        *(uint32_t*)(O0 + c)        = h01;
        *(uint32_t*)(O0 + 1024 + c) = l01;
        *(uint32_t*)(O1 + c)        = h23;
        *(uint32_t*)(O1 + 1024 + c) = l23;
    }
}

// ---------------------------------------------------------------------------
// kernel_launch: graph-capturable, allocation-free.
// Input order: x, masks, Wq, bq, Wk, bk, Wv, bv, Wo, bo
// ---------------------------------------------------------------------------
extern "C" void kernel_launch(void* const* d_in, const int* in_sizes, int n_in,
                              void* d_out, int out_size)
{
    const float* x     = (const float*)d_in[0];
    const int*   masks = (const int*)  d_in[1];
    const float* Wq    = (const float*)d_in[2];
    const float* bq    = (const float*)d_in[3];
    const float* Wk    = (const float*)d_in[4];
    const float* bk    = (const float*)d_in[5];
    const float* Wv    = (const float*)d_in[6];
    const float* bv    = (const float*)d_in[7];
    const float* Wo    = (const float*)d_in[8];
    const float* bo    = (const float*)d_in[9];
    float* out = (float*)d_out;

    __nv_bfloat16 *xs, *wqkv, *wo2, *qs, *ks, *vs, *attb;
    cudaGetSymbolAddress((void**)&xs,   g_xs);
    cudaGetSymbolAddress((void**)&wqkv, g_wqkv);
    cudaGetSymbolAddress((void**)&wo2,  g_wo);
    cudaGetSymbolAddress((void**)&qs,   g_qs);
    cudaGetSymbolAddress((void**)&ks,   g_ks);
    cudaGetSymbolAddress((void**)&vs,   g_vs);
    cudaGetSymbolAddress((void**)&attb, g_attb);

    cudaFuncSetAttribute(gemm3,    cudaFuncAttributeMaxDynamicSharedMemorySize, GSMEM);
    cudaFuncSetAttribute(attn_mma, cudaFuncAttributeMaxDynamicSharedMemorySize, ATTN_SMEM);

    // fp32 -> bf16 hi/lo conversions (one launch for x, one for all weights)
    split_x_kernel<<<(Mdim * Ddim) / 4 / 256, 256>>>(x, xs);
    dim3 wgrid(32, 32, 4), wblk(32, 8);
    wsplit4_kernel<<<wgrid, wblk>>>(Wq, Wk, Wv, Wo, wqkv, wo2);

    // Fused QKV projection -> bf16 split outputs (Q pre-scaled by 1/8)
    dim3 gq(3 * Ddim / 128, Mdim / 128);   // (24, 64)
    gemm3<<<gq, 256, GSMEM>>>(xs, wqkv, bq, bk, bv, qs, ks, vs, nullptr, 0, Ddim);

    // Tensor-core flash attention -> bf16 split
    dim3 ga(Sdim / 64, Hdim, Bdim);        // (16, 16, 8)
    attn_mma<<<ga, 128, ATTN_SMEM>>>(qs, ks, vs, masks, attb);

    // Output projection -> fp32
    dim3 go(Ddim / 128, Mdim / 128);       // (8, 64)
    gemm3<<<go, 256, GSMEM>>>(attb, wo2, bo, nullptr, nullptr, nullptr, nullptr,
                              nullptr, out, 1, Ddim);
}

// round 17
// speedup vs baseline: 1.0525x; 1.0525x over previous
#include <cuda_runtime.h>
#include <cuda_bf16.h>
#include <cuda_fp16.h>
#include <cstdint>

// Problem dims (fixed by the reference)
#define Bdim  8
#define Sdim  1024
#define Ddim  1024
#define Hdim  16
#define DKdim 64
#define Mdim  (Bdim * Sdim)   // 8192 rows
#define K2    2048            // split width (hi | lo)

// log2(e), folded into Q's projection scale so softmax uses exp2
#define LOG2E 1.4426950408889634f

// ---------------------------------------------------------------------------
// Scratch (__device__ globals; no cudaMalloc allowed)
// ---------------------------------------------------------------------------
__device__ __nv_bfloat16 g_xs  [(size_t)Mdim * K2];        // x split [M,2048]
__device__ __nv_bfloat16 g_wqkv[(size_t)3 * Ddim * K2];    // Wq|Wk|Wv ^T split
__device__ __nv_bfloat16 g_wo  [(size_t)Ddim * K2];        // Wo^T split
__device__ __nv_bfloat16 g_qs  [(size_t)Mdim * K2];        // Q bf16 split (pre-scaled)
__device__ __nv_bfloat16 g_ks  [(size_t)Mdim * K2];        // K bf16 split
__device__ __nv_bfloat16 g_vs  [(size_t)Mdim * K2];        // V fp16 split (raw bits)
__device__ __nv_bfloat16 g_attb[(size_t)Mdim * K2];        // attn out bf16 split

// ---------------------------------------------------------------------------
// Helpers (arch-agnostic PTX only: cp.async, ldmatrix, mma.sync)
// ---------------------------------------------------------------------------
__device__ __forceinline__ uint32_t smem_u32(const void* p) {
    uint32_t a;
    asm("{ .reg .u64 t; cvta.to.shared.u64 t, %1; cvt.u32.u64 %0, t; }"
        : "=r"(a) : "l"(p));
    return a;
}

__device__ __forceinline__ void cp_async16(uint32_t dst, const void* src) {
    asm volatile("cp.async.cg.shared.global [%0], [%1], 16;"
                 :: "r"(dst), "l"(src) : "memory");
}
__device__ __forceinline__ void cp_commit() {
    asm volatile("cp.async.commit_group;" ::: "memory");
}
template <int N>
__device__ __forceinline__ void cp_wait() {
    asm volatile("cp.async.wait_group %0;" :: "n"(N) : "memory");
}

__device__ __forceinline__ void ldsm_x4(uint32_t& r0, uint32_t& r1,
                                        uint32_t& r2, uint32_t& r3, uint32_t a) {
    asm volatile("ldmatrix.sync.aligned.m8n8.x4.shared.b16 {%0,%1,%2,%3}, [%4];"
                 : "=r"(r0), "=r"(r1), "=r"(r2), "=r"(r3) : "r"(a));
}
__device__ __forceinline__ void ldsm_x4_t(uint32_t& r0, uint32_t& r1,
                                          uint32_t& r2, uint32_t& r3, uint32_t a) {
    asm volatile("ldmatrix.sync.aligned.m8n8.x4.trans.shared.b16 {%0,%1,%2,%3}, [%4];"
                 : "=r"(r0), "=r"(r1), "=r"(r2), "=r"(r3) : "r"(a));
}

// bf16 mma (QK^T, projections)
__device__ __forceinline__ void mma_bf16(float* d, const uint32_t* a,
                                         const uint32_t* b) {
    asm volatile(
        "mma.sync.aligned.m16n8k16.row.col.f32.bf16.bf16.f32 "
        "{%0,%1,%2,%3}, {%4,%5,%6,%7}, {%8,%9}, {%0,%1,%2,%3};"
        : "+f"(d[0]), "+f"(d[1]), "+f"(d[2]), "+f"(d[3])
        : "r"(a[0]), "r"(a[1]), "r"(a[2]), "r"(a[3]), "r"(b[0]), "r"(b[1]));
}
// fp16 mma (P x V)
__device__ __forceinline__ void mma_f16(float* d, const uint32_t* a,
                                        const uint32_t* b) {
    asm volatile(
        "mma.sync.aligned.m16n8k16.row.col.f32.f16.f16.f32 "
        "{%0,%1,%2,%3}, {%4,%5,%6,%7}, {%8,%9}, {%0,%1,%2,%3};"
        : "+f"(d[0]), "+f"(d[1]), "+f"(d[2]), "+f"(d[3])
        : "r"(a[0]), "r"(a[1]), "r"(a[2]), "r"(a[3]), "r"(b[0]), "r"(b[1]));
}

// Pack (x -> low, y -> high) into bf16x2 / f16x2 in ONE cvt instruction.
__device__ __forceinline__ uint32_t cvt2_bf16(float x, float y) {
    uint32_t r;
    asm("cvt.rn.bf16x2.f32 %0, %1, %2;" : "=r"(r) : "f"(y), "f"(x));
    return r;
}
__device__ __forceinline__ uint32_t cvt2_f16(float x, float y) {
    uint32_t r;
    asm("cvt.rn.f16x2.f32 %0, %1, %2;" : "=r"(r) : "f"(y), "f"(x));
    return r;
}

// Pack (x,y) -> bf16x2 hi-plane + residual lo-plane.
#define SPLITPK(dh, dl, x, y)                                                  \
    {                                                                          \
        float _x = (x), _y = (y);                                              \
        uint32_t _h = cvt2_bf16(_x, _y);                                       \
        float _fx = __uint_as_float(_h << 16);                                 \
        float _fy = __uint_as_float(_h & 0xffff0000u);                         \
        (dh) = _h;                                                             \
        (dl) = cvt2_bf16(_x - _fx, _y - _fy);                                  \
    }
// fp16 variant (for the V planes)
#define SPLITPK16(dh, dl, x, y)                                                \
    {                                                                          \
        float _x = (x), _y = (y);                                              \
        uint32_t _h = cvt2_f16(_x, _y);                                        \
        __half2 _hh = *reinterpret_cast<__half2*>(&_h);                        \
        (dh) = _h;                                                             \
        (dl) = cvt2_f16(_x - __low2float(_hh), _y - __high2float(_hh));        \
    }

// Swizzle inside a [rows x 32 bf16] tile (64B rows, 4 chunks)
__device__ __forceinline__ uint32_t swz(int row, int chunk) {
    return (uint32_t)(row * 64 + ((chunk ^ ((row >> 1) & 3)) << 4));
}
// Swizzle inside a [rows x 64 bf16] tile (128B rows, 8 chunks)
__device__ __forceinline__ uint32_t sw64o(int row, int chunk) {
    return (uint32_t)(row * 128 + ((chunk ^ (row & 7)) << 4));
}

// ---------------------------------------------------------------------------
// Conversion kernels
// ---------------------------------------------------------------------------
__global__ __launch_bounds__(256) void split_x_kernel(const float* __restrict__ X,
                                                      __nv_bfloat16* __restrict__ Y) {
    size_t t = (size_t)blockIdx.x * 256 + threadIdx.x;
    size_t e = t * 4;
    int row = (int)(e >> 10);
    int col = (int)(e & 1023);
    float4 v = *(const float4*)(X + e);
    uint2 ph, pl;
    SPLITPK(ph.x, pl.x, v.x, v.y);
    SPLITPK(ph.y, pl.y, v.z, v.w);
    *(uint2*)(Y + (size_t)row * K2 + col)        = ph;
    *(uint2*)(Y + (size_t)row * K2 + 1024 + col) = pl;
}

// All four weights in one launch (z selects W); dest: Wq|Wk|Wv -> Yqkv, Wo -> Yo
__global__ __launch_bounds__(256) void wsplit4_kernel(
    const float* __restrict__ W0, const float* __restrict__ W1,
    const float* __restrict__ W2, const float* __restrict__ W3,
    __nv_bfloat16* __restrict__ Yqkv, __nv_bfloat16* __restrict__ Yo)
{
    __shared__ float t[32][33];
    const int z = blockIdx.z;
    const float* W = (z == 0) ? W0 : (z == 1) ? W1 : (z == 2) ? W2 : W3;
    __nv_bfloat16* Y = (z < 3) ? (Yqkv + (size_t)z * Ddim * K2) : Yo;

    int k0 = blockIdx.x * 32, n0 = blockIdx.y * 32;
    int tx = threadIdx.x, ty = threadIdx.y;   // 32 x 8
#pragma unroll
    for (int i = 0; i < 4; i++)
        t[ty + 8 * i][tx] = W[(size_t)(k0 + ty + 8 * i) * 1024 + n0 + tx];
    __syncthreads();
#pragma unroll
    for (int i = 0; i < 4; i++) {
        int n = n0 + ty + 8 * i;
        float v = t[tx][ty + 8 * i];
        __nv_bfloat16 h = __float2bfloat16(v);
        __nv_bfloat16 l = __float2bfloat16(v - __bfloat162float(h));
        Y[(size_t)n * K2 + k0 + tx]        = h;
        Y[(size_t)n * K2 + 1024 + k0 + tx] = l;
    }
}

// ---------------------------------------------------------------------------
// bf16-split GEMM (3-term), all-planes-per-chunk, 2-stage pipeline (proven).
// mode 0: fused QKV epilogue — Q: bf16 split, scale 0.125*log2e;
//         K: bf16 split; V: fp16 split (for fp16 PV mma).
// mode 1: fp32 out Cf = A*B^T + bias0.
// ---------------------------------------------------------------------------
#define GSMEM (2 * 32768)

__global__ __launch_bounds__(256) void gemm3(
    const __nv_bfloat16* __restrict__ A2,
    const __nv_bfloat16* __restrict__ B2,
    const float* __restrict__ bias0,
    const float* __restrict__ bias1,
    const float* __restrict__ bias2,
    __nv_bfloat16* __restrict__ Cq,
    __nv_bfloat16* __restrict__ Ck,
    __nv_bfloat16* __restrict__ Cv,
    float* __restrict__ Cf,
    int mode, int N)
{
    extern __shared__ __align__(128) char smraw[];
    const uint32_t sm0 = smem_u32(smraw);

    const int tid  = threadIdx.x;
    const int lane = tid & 31;
    const int warp = tid >> 5;
    const int wm   = warp & 1;
    const int wn   = warp >> 1;
    const int brow = blockIdx.y * 128;
    const int bcol = blockIdx.x * 128;

    float acc[4][4][4];
#pragma unroll
    for (int i = 0; i < 4; i++)
#pragma unroll
        for (int j = 0; j < 4; j++)
#pragma unroll
            for (int e = 0; e < 4; e++) acc[i][j][e] = 0.f;

    const int r0 = tid >> 2,         c0 = tid & 3;
    const int r1 = (tid + 256) >> 2, c1 = (tid + 256) & 3;
    const uint32_t so0 = swz(r0, c0), so1 = swz(r1, c1);

    const int lrow  = lane & 15;
    const int lksel = lane >> 4;

#define ISSUE(it, stage)                                                       \
    do {                                                                       \
        int _kt = (it);                                                        \
        const __nv_bfloat16* _A = A2 + (size_t)brow * K2 + _kt * 32;           \
        const __nv_bfloat16* _B = B2 + (size_t)bcol * K2 + _kt * 32;           \
        uint32_t _s = sm0 + (stage) * 32768;                                   \
        cp_async16(_s + so0,          _A + (size_t)r0 * K2 + c0 * 8);          \
        cp_async16(_s + so1,          _A + (size_t)r1 * K2 + c1 * 8);          \
        cp_async16(_s + 8192  + so0,  _A + (size_t)r0 * K2 + 1024 + c0 * 8);   \
        cp_async16(_s + 8192  + so1,  _A + (size_t)r1 * K2 + 1024 + c1 * 8);   \
        cp_async16(_s + 16384 + so0,  _B + (size_t)r0 * K2 + c0 * 8);          \
        cp_async16(_s + 16384 + so1,  _B + (size_t)r1 * K2 + c1 * 8);          \
        cp_async16(_s + 24576 + so0,  _B + (size_t)r0 * K2 + 1024 + c0 * 8);   \
        cp_async16(_s + 24576 + so1,  _B + (size_t)r1 * K2 + 1024 + c1 * 8);   \
        cp_commit();                                                           \
    } while (0)

    ISSUE(0, 0);

    for (int it = 0; it < 32; it++) {
        const int cur = it & 1;
        if (it + 1 < 32) {
            ISSUE(it + 1, cur ^ 1);
            cp_wait<1>();
        } else {
            cp_wait<0>();
        }
        __syncthreads();

        const uint32_t sAh = sm0 + cur * 32768;
        const uint32_t sAl = sAh + 8192;
        const uint32_t sBh = sAh + 16384;
        const uint32_t sBl = sAh + 24576;

#pragma unroll
        for (int ks = 0; ks < 2; ks++) {
            const int chunk = ks * 2 + lksel;
            uint32_t ah[4][4], al[4][4], b[4][2];
#pragma unroll
            for (int mi = 0; mi < 4; mi++)
                ldsm_x4(ah[mi][0], ah[mi][1], ah[mi][2], ah[mi][3],
                        sAh + swz(wm * 64 + mi * 16 + lrow, chunk));
#pragma unroll
            for (int nj = 0; nj < 2; nj++) {
                uint32_t t0, t1, t2, t3;
                ldsm_x4(t0, t1, t2, t3,
                        sBh + swz(wn * 32 + nj * 16 + lrow, chunk));
                b[nj * 2 + 0][0] = t0;  b[nj * 2 + 1][0] = t1;
                b[nj * 2 + 0][1] = t2;  b[nj * 2 + 1][1] = t3;
            }
#pragma unroll
            for (int mi = 0; mi < 4; mi++)
#pragma unroll
                for (int ni = 0; ni < 4; ni++)
                    mma_bf16(acc[mi][ni], ah[mi], b[ni]);

#pragma unroll
            for (int mi = 0; mi < 4; mi++)
                ldsm_x4(al[mi][0], al[mi][1], al[mi][2], al[mi][3],
                        sAl + swz(wm * 64 + mi * 16 + lrow, chunk));
#pragma unroll
            for (int mi = 0; mi < 4; mi++)
#pragma unroll
                for (int ni = 0; ni < 4; ni++)
                    mma_bf16(acc[mi][ni], al[mi], b[ni]);

#pragma unroll
            for (int nj = 0; nj < 2; nj++) {
                uint32_t t0, t1, t2, t3;
                ldsm_x4(t0, t1, t2, t3,
                        sBl + swz(wn * 32 + nj * 16 + lrow, chunk));
                b[nj * 2 + 0][0] = t0;  b[nj * 2 + 1][0] = t1;
                b[nj * 2 + 0][1] = t2;  b[nj * 2 + 1][1] = t3;
            }
#pragma unroll
            for (int mi = 0; mi < 4; mi++)
#pragma unroll
                for (int ni = 0; ni < 4; ni++)
                    mma_bf16(acc[mi][ni], ah[mi], b[ni]);
        }
        __syncthreads();
    }
#undef ISSUE

    // ---- Epilogue ----
    if (mode == 0) {
        const int region = bcol >> 10;                  // 0:Q 1:K 2:V
        __nv_bfloat16* Cs  = (region == 0) ? Cq : (region == 1) ? Ck : Cv;
        const float*   bia = (region == 0) ? bias0 : (region == 1) ? bias1 : bias2;
        // Q carries 1/sqrt(DK) AND log2(e) so attention can use exp2 directly.
        const float    scale = (region == 0) ? (0.125f * LOG2E) : 1.0f;
        const int ncb = bcol & 1023;
#pragma unroll
        for (int mi = 0; mi < 4; mi++) {
#pragma unroll
            for (int ni = 0; ni < 4; ni++) {
                int r = brow + wm * 64 + mi * 16 + (lane >> 2);
                int c = ncb + wn * 32 + ni * 8 + (lane & 3) * 2;
                float bx = bia[c], by = bia[c + 1];
                float x0 = (acc[mi][ni][0] + bx) * scale;
                float x1 = (acc[mi][ni][1] + by) * scale;
                float x2 = (acc[mi][ni][2] + bx) * scale;
                float x3 = (acc[mi][ni][3] + by) * scale;
                uint32_t h01, l01, h23, l23;
                if (region == 2) {      // V -> fp16 hi/lo planes
                    SPLITPK16(h01, l01, x0, x1);
                    SPLITPK16(h23, l23, x2, x3);
                } else {                // Q,K -> bf16 hi/lo planes
                    SPLITPK(h01, l01, x0, x1);
                    SPLITPK(h23, l23, x2, x3);
                }
                *(uint32_t*)(Cs + (size_t)r * K2 + c)              = h01;
                *(uint32_t*)(Cs + (size_t)r * K2 + 1024 + c)       = l01;
                *(uint32_t*)(Cs + (size_t)(r + 8) * K2 + c)        = h23;
                *(uint32_t*)(Cs + (size_t)(r + 8) * K2 + 1024 + c) = l23;
            }
        }
    } else {
#pragma unroll
        for (int mi = 0; mi < 4; mi++) {
#pragma unroll
            for (int ni = 0; ni < 4; ni++) {
                int r = brow + wm * 64 + mi * 16 + (lane >> 2);
                int c = bcol + wn * 32 + ni * 8 + (lane & 3) * 2;
                float bx = bias0[c], by = bias0[c + 1];
                *(float2*)(Cf + (size_t)r * N + c) =
                    make_float2(acc[mi][ni][0] + bx, acc[mi][ni][1] + by);
                *(float2*)(Cf + (size_t)(r + 8) * N + c) =
                    make_float2(acc[mi][ni][2] + bx, acc[mi][ni][3] + by);
            }
        }
    }
}

// ---------------------------------------------------------------------------
// Tensor-core flash attention.
// QK^T: 3-term bf16 split (absolute logit accuracy needed).
// PV:   P in fp16 (single plane, 2^-11 rel err on weights in [0,1]) x
//       V in fp16 hi/lo (2 terms) -> 2 mma passes instead of 3.
// Softmax in exp2 domain (log2e pre-folded into Q scale).
// CTA = 64 queries of one (b,h); 4 warps; 2-stage pipeline; 3 CTAs/SM.
// ---------------------------------------------------------------------------
#define ATTN_SMEM (65536 + 512)

__global__ __launch_bounds__(128) void attn_mma(
    const __nv_bfloat16* __restrict__ Qs,
    const __nv_bfloat16* __restrict__ Ks,
    const __nv_bfloat16* __restrict__ Vsrc,
    const int* __restrict__ masks,
    __nv_bfloat16* __restrict__ Ob)
{
    extern __shared__ __align__(128) char smraw[];
    const uint32_t sb = smem_u32(smraw);
    int* mskp = (int*)(smraw + 65536);

    const int tid  = threadIdx.x;
    const int lane = tid & 31;
    const int warp = tid >> 5;
    const int lrow  = lane & 15;
    const int lksel = lane >> 4;
    const int b = blockIdx.z, h = blockIdx.y;
    const int q0 = blockIdx.x * 64;

    const __nv_bfloat16* Qg = Qs   + (size_t)(b * Sdim + q0) * K2 + h * 64;
    const __nv_bfloat16* Kg = Ks   + (size_t)(b * Sdim) * K2 + h * 64;
    const __nv_bfloat16* Vg = Vsrc + (size_t)(b * Sdim) * K2 + h * 64;

    // ---- stage Q (hi/lo) through smem, extract fragments into registers ----
#pragma unroll
    for (int i = 0; i < 4; i++) {
        int idx = tid + i * 128;
        int r = idx >> 3, c = idx & 7;
        uint32_t off = sw64o(r, c);
        cp_async16(sb + off,        Qg + (size_t)r * K2 + c * 8);
        cp_async16(sb + 8192 + off, Qg + (size_t)r * K2 + 1024 + c * 8);
    }
    cp_commit();
    cp_wait<0>();
    __syncthreads();

    uint32_t aqh[4][4], aql[4][4];
#pragma unroll
    for (int ks = 0; ks < 4; ks++) {
        uint32_t off = sw64o(warp * 16 + lrow, ks * 2 + lksel);
        ldsm_x4(aqh[ks][0], aqh[ks][1], aqh[ks][2], aqh[ks][3], sb + off);
        ldsm_x4(aql[ks][0], aql[ks][1], aql[ks][2], aql[ks][3], sb + 8192 + off);
    }
    __syncthreads();

#define AISSUE(kt, stg)                                                         \
    do {                                                                        \
        const __nv_bfloat16* _K = Kg + (size_t)(kt) * 64 * K2;                  \
        const __nv_bfloat16* _V = Vg + (size_t)(kt) * 64 * K2;                  \
        uint32_t _s = sb + (stg) * 32768;                                       \
        _Pragma("unroll")                                                       \
        for (int _i = 0; _i < 4; _i++) {                                        \
            int _idx = tid + _i * 128;                                          \
            int _r = _idx >> 3, _c = _idx & 7;                                  \
            uint32_t _o = sw64o(_r, _c);                                        \
            cp_async16(_s + _o,         _K + (size_t)_r * K2 + _c * 8);         \
            cp_async16(_s + 8192 + _o,  _K + (size_t)_r * K2 + 1024 + _c * 8);  \
            cp_async16(_s + 16384 + _o, _V + (size_t)_r * K2 + _c * 8);         \
            cp_async16(_s + 24576 + _o, _V + (size_t)_r * K2 + 1024 + _c * 8);  \
        }                                                                       \
        if (tid < 64) mskp[(stg) * 64 + tid] = masks[b * Sdim + (kt) * 64 + tid]; \
        cp_commit();                                                            \
    } while (0)

    float m0 = -1e30f, m1 = -1e30f, l0 = 0.f, l1 = 0.f;
    float o[8][4];
#pragma unroll
    for (int dt = 0; dt < 8; dt++)
#pragma unroll
        for (int e = 0; e < 4; e++) o[dt][e] = 0.f;

    AISSUE(0, 0);

    for (int kt = 0; kt < 16; kt++) {
        const int st = kt & 1;
        if (kt + 1 < 16) {
            AISSUE(kt + 1, st ^ 1);
            cp_wait<1>();
        } else {
            cp_wait<0>();
        }
        __syncthreads();

        const uint32_t sK  = sb + st * 32768;
        const uint32_t sKl = sK + 8192;
        const uint32_t sV  = sK + 16384;
        const uint32_t sVl = sK + 24576;
        const int* mk = mskp + st * 64;

        // -------- scores: S = Qhi*Khi + Qlo*Khi + Qhi*Klo (log2 domain) -----
        float sc[8][4];
#pragma unroll
        for (int nt = 0; nt < 8; nt++)
#pragma unroll
            for (int e = 0; e < 4; e++) sc[nt][e] = 0.f;

#pragma unroll
        for (int ks = 0; ks < 4; ks++) {
            uint32_t bk[8][2];
#pragma unroll
            for (int np = 0; np < 4; np++) {
                uint32_t t0, t1, t2, t3;
                ldsm_x4(t0, t1, t2, t3, sK + sw64o(np * 16 + lrow, ks * 2 + lksel));
                bk[np * 2][0] = t0;  bk[np * 2][1] = t2;
                bk[np * 2 + 1][0] = t1;  bk[np * 2 + 1][1] = t3;
            }
#pragma unroll
            for (int nt = 0; nt < 8; nt++) mma_bf16(sc[nt], aqh[ks], bk[nt]);
#pragma unroll
            for (int nt = 0; nt < 8; nt++) mma_bf16(sc[nt], aql[ks], bk[nt]);
#pragma unroll
            for (int np = 0; np < 4; np++) {
                uint32_t t0, t1, t2, t3;
                ldsm_x4(t0, t1, t2, t3, sKl + sw64o(np * 16 + lrow, ks * 2 + lksel));
                bk[np * 2][0] = t0;  bk[np * 2][1] = t2;
                bk[np * 2 + 1][0] = t1;  bk[np * 2 + 1][1] = t3;
            }
#pragma unroll
            for (int nt = 0; nt < 8; nt++) mma_bf16(sc[nt], aqh[ks], bk[nt]);
        }

        // -------- mask (warp-uniform fast path when all mask bits set) ------
        {
            bool anyz = (mk[lane] == 0) | (mk[lane + 32] == 0);
            if (__ballot_sync(0xffffffffu, anyz)) {
#pragma unroll
                for (int nt = 0; nt < 8; nt++) {
                    int k0 = nt * 8 + 2 * (lane & 3);
                    if (mk[k0] == 0)     { sc[nt][0] = -1e9f; sc[nt][2] = -1e9f; }
                    if (mk[k0 + 1] == 0) { sc[nt][1] = -1e9f; sc[nt][3] = -1e9f; }
                }
            }
        }

        // -------- online softmax (exp2 domain; rows lane>>2 and +8) ---------
        float mx0 = -1e30f, mx1 = -1e30f;
#pragma unroll
        for (int nt = 0; nt < 8; nt++) {
            mx0 = fmaxf(mx0, fmaxf(sc[nt][0], sc[nt][1]));
            mx1 = fmaxf(mx1, fmaxf(sc[nt][2], sc[nt][3]));
        }
        mx0 = fmaxf(mx0, __shfl_xor_sync(0xffffffffu, mx0, 1));
        mx0 = fmaxf(mx0, __shfl_xor_sync(0xffffffffu, mx0, 2));
        mx1 = fmaxf(mx1, __shfl_xor_sync(0xffffffffu, mx1, 1));
        mx1 = fmaxf(mx1, __shfl_xor_sync(0xffffffffu, mx1, 2));

        float nm0 = fmaxf(m0, mx0), nm1 = fmaxf(m1, mx1);
        float cr0 = exp2f(m0 - nm0), cr1 = exp2f(m1 - nm1);
        float s0 = 0.f, s1 = 0.f;
#pragma unroll
        for (int nt = 0; nt < 8; nt++) {
            sc[nt][0] = exp2f(sc[nt][0] - nm0);  s0 += sc[nt][0];
            sc[nt][1] = exp2f(sc[nt][1] - nm0);  s0 += sc[nt][1];
            sc[nt][2] = exp2f(sc[nt][2] - nm1);  s1 += sc[nt][2];
            sc[nt][3] = exp2f(sc[nt][3] - nm1);  s1 += sc[nt][3];
        }
        s0 += __shfl_xor_sync(0xffffffffu, s0, 1);
        s0 += __shfl_xor_sync(0xffffffffu, s0, 2);
        s1 += __shfl_xor_sync(0xffffffffu, s1, 1);
        s1 += __shfl_xor_sync(0xffffffffu, s1, 2);
        l0 = l0 * cr0 + s0;  l1 = l1 * cr1 + s1;
        m0 = nm0;  m1 = nm1;
#pragma unroll
        for (int dt = 0; dt < 8; dt++) {
            o[dt][0] *= cr0;  o[dt][1] *= cr0;
            o[dt][2] *= cr1;  o[dt][3] *= cr1;
        }

        // -------- O += P_f16 * (Vhi + Vlo)  (2 mma passes) -------------------
#pragma unroll
        for (int ks = 0; ks < 4; ks++) {
            uint32_t ph[4];
            ph[0] = cvt2_f16(sc[2 * ks][0],     sc[2 * ks][1]);
            ph[1] = cvt2_f16(sc[2 * ks][2],     sc[2 * ks][3]);
            ph[2] = cvt2_f16(sc[2 * ks + 1][0], sc[2 * ks + 1][1]);
            ph[3] = cvt2_f16(sc[2 * ks + 1][2], sc[2 * ks + 1][3]);

            uint32_t bv[8][2];
#pragma unroll
            for (int dp = 0; dp < 4; dp++) {
                uint32_t t0, t1, t2, t3;
                ldsm_x4_t(t0, t1, t2, t3, sV + sw64o(ks * 16 + lrow, dp * 2 + lksel));
                bv[dp * 2][0] = t0;  bv[dp * 2][1] = t1;
                bv[dp * 2 + 1][0] = t2;  bv[dp * 2 + 1][1] = t3;
            }
#pragma unroll
            for (int dt = 0; dt < 8; dt++) mma_f16(o[dt], ph, bv[dt]);
#pragma unroll
            for (int dp = 0; dp < 4; dp++) {
                uint32_t t0, t1, t2, t3;
                ldsm_x4_t(t0, t1, t2, t3, sVl + sw64o(ks * 16 + lrow, dp * 2 + lksel));
                bv[dp * 2][0] = t0;  bv[dp * 2][1] = t1;
                bv[dp * 2 + 1][0] = t2;  bv[dp * 2 + 1][1] = t3;
            }
#pragma unroll
            for (int dt = 0; dt < 8; dt++) mma_f16(o[dt], ph, bv[dt]);
        }
        __syncthreads();
    }
#undef AISSUE

    // -------- normalize + write bf16 hi/lo split --------
    float i0 = 1.f / l0, i1 = 1.f / l1;
    int rg = b * Sdim + q0 + warp * 16 + (lane >> 2);
    int cb = h * 64 + 2 * (lane & 3);
    __nv_bfloat16* O0 = Ob + (size_t)rg * K2;
    __nv_bfloat16* O1 = Ob + (size_t)(rg + 8) * K2;
#pragma unroll
    for (int dt = 0; dt < 8; dt++) {
        int c = cb + dt * 8;
        uint32_t h01, l01, h23, l23;
        SPLITPK(h01, l01, o[dt][0] * i0, o[dt][1] * i0);
        SPLITPK(h23, l23, o[dt][2] * i1, o[dt][3] * i1);
        *(uint32_t*)(O0 + c)        = h01;
        *(uint32_t*)(O0 + 1024 + c) = l01;
        *(uint32_t*)(O1 + c)        = h23;
        *(uint32_t*)(O1 + 1024 + c) = l23;
    }
}

// ---------------------------------------------------------------------------
// kernel_launch: graph-capturable, allocation-free.
// Input order: x, masks, Wq, bq, Wk, bk, Wv, bv, Wo, bo
// ---------------------------------------------------------------------------
extern "C" void kernel_launch(void* const* d_in, const int* in_sizes, int n_in,
                              void* d_out, int out_size)
{
    const float* x     = (const float*)d_in[0];
    const int*   masks = (const int*)  d_in[1];
    const float* Wq    = (const float*)d_in[2];
    const float* bq    = (const float*)d_in[3];
    const float* Wk    = (const float*)d_in[4];
    const float* bk    = (const float*)d_in[5];
    const float* Wv    = (const float*)d_in[6];
    const float* bv    = (const float*)d_in[7];
    const float* Wo    = (const float*)d_in[8];
    const float* bo    = (const float*)d_in[9];
    float* out = (float*)d_out;

    __nv_bfloat16 *xs, *wqkv, *wo2, *qs, *ks, *vs, *attb;
    cudaGetSymbolAddress((void**)&xs,   g_xs);
    cudaGetSymbolAddress((void**)&wqkv, g_wqkv);
    cudaGetSymbolAddress((void**)&wo2,  g_wo);
    cudaGetSymbolAddress((void**)&qs,   g_qs);
    cudaGetSymbolAddress((void**)&ks,   g_ks);
    cudaGetSymbolAddress((void**)&vs,   g_vs);
    cudaGetSymbolAddress((void**)&attb, g_attb);

    cudaFuncSetAttribute(gemm3,    cudaFuncAttributeMaxDynamicSharedMemorySize, GSMEM);
    cudaFuncSetAttribute(attn_mma, cudaFuncAttributeMaxDynamicSharedMemorySize, ATTN_SMEM);

    // fp32 -> bf16 hi/lo conversions (one launch for x, one for all weights)
    split_x_kernel<<<(Mdim * Ddim) / 4 / 256, 256>>>(x, xs);
    dim3 wgrid(32, 32, 4), wblk(32, 8);
    wsplit4_kernel<<<wgrid, wblk>>>(Wq, Wk, Wv, Wo, wqkv, wo2);

    // Fused QKV projection (Q pre-scaled by 0.125*log2e; V emitted as fp16 split)
    dim3 gq(3 * Ddim / 128, Mdim / 128);   // (24, 64)
    gemm3<<<gq, 256, GSMEM>>>(xs, wqkv, bq, bk, bv, qs, ks, vs, nullptr, 0, Ddim);

    // Tensor-core flash attention -> bf16 split
    dim3 ga(Sdim / 64, Hdim, Bdim);        // (16, 16, 8)
    attn_mma<<<ga, 128, ATTN_SMEM>>>(qs, ks, vs, masks, attb);

    // Output projection -> fp32
    dim3 go(Ddim / 128, Mdim / 128);       // (8, 64)
    gemm3<<<go, 256, GSMEM>>>(attb, wo2, bo, nullptr, nullptr, nullptr, nullptr,
                              nullptr, out, 1, Ddim);
}